// round 14
// baseline (speedup 1.0000x reference)
#include <cuda_runtime.h>
#include <cuda_bf16.h>

static constexpr int NPIX   = 256 * 256;
static constexpr int NBATCH = 16;
static constexpr int NBINS  = 64;
static constexpr int BPB    = 9;
static constexpr int NBLK   = BPB * NBATCH;   // 144 <= 148 SMs, 1 CTA/SM
static constexpr int TPB    = 1024;
static constexpr int OUT_N  = NBATCH * NBINS * NBINS;
static constexpr int CHUNK  = (NPIX + BPB - 1) / BPB;   // 7282 px per block
static constexpr int KT     = 256;                      // pixels per MMA tile
static constexpr int NT     = (CHUNK + KT - 1) / KT;    // 29 tiles

// Padded tiles: 64 rows x 256 bf16, pitch 528 B (512+16 -> conflict-free ldmatrix)
static constexpr int APITCH = 528;
static constexpr int T_SZ   = 64 * APITCH;              // 33792 B per tile
static constexpr int SET_BYTES = 2 * T_SZ;              // A + B per set
static constexpr int DUMMY_OFF = 2 * SET_BYTES;         // after both sets
static constexpr int SM_ZERO   = DUMMY_OFF + TPB * 8;   // tiles + dummy region
static constexpr int SMEM_BYTES = SM_ZERO + 1024;       // + align slack

__device__ unsigned g_slot[NBLK][4];
__device__ unsigned g_cnt;

__device__ __forceinline__ unsigned fenc(float f) {
    unsigned b = __float_as_uint(f);
    return (b & 0x80000000u) ? ~b : (b | 0x80000000u);
}
__device__ __forceinline__ float fdec(unsigned e) {
    unsigned b = (e & 0x80000000u) ? (e & 0x7fffffffu) : ~e;
    return __uint_as_float(b);
}
__device__ __forceinline__ unsigned smem_u32(const void* p) {
    unsigned a;
    asm("{ .reg .u64 t; cvta.to.shared.u64 t, %1; cvt.u32.u64 %0, t; }"
        : "=r"(a) : "l"(p));
    return a;
}
__device__ __forceinline__ void sts16(unsigned a, unsigned short v) {
    asm volatile("st.shared.u16 [%0], %1;" :: "r"(a), "h"(v) : "memory");
}
__device__ __forceinline__ void barset(int id) {
    asm volatile("bar.sync %0, %1;" :: "r"(id), "r"(512) : "memory");
}
__device__ __forceinline__ void ldsm4(unsigned* r, unsigned addr) {
    asm volatile("ldmatrix.sync.aligned.m8n8.x4.shared.b16 {%0,%1,%2,%3}, [%4];"
                 : "=r"(r[0]), "=r"(r[1]), "=r"(r[2]), "=r"(r[3]) : "r"(addr));
}
__device__ __forceinline__ void mma16816(float* c, const unsigned* a,
                                         unsigned b0, unsigned b1) {
    asm volatile(
        "mma.sync.aligned.m16n8k16.row.col.f32.bf16.bf16.f32 "
        "{%0,%1,%2,%3}, {%4,%5,%6,%7}, {%8,%9}, {%0,%1,%2,%3};"
        : "+f"(c[0]), "+f"(c[1]), "+f"(c[2]), "+f"(c[3])
        : "r"(a[0]), "r"(a[1]), "r"(a[2]), "r"(a[3]), "r"(b0), "r"(b1));
}

// B-spline weight for tap i of fractional offset u
__device__ __forceinline__ float bw(float u, int tap) {
    float v = 1.0f - u;
    if (tap == 0) return v * v * v * (1.0f / 6.0f);
    if (tap == 1) return fmaf(-u * u, fmaf(-0.5f, u, 1.0f), 2.0f / 3.0f);
    if (tap == 2) return fmaf(-v * v, fmaf(-0.5f, v, 1.0f), 2.0f / 3.0f);
    return u * u * u * (1.0f / 6.0f);
}

__global__ __launch_bounds__(TPB, 1)
void k_fused(const float* __restrict__ ref,
             const float* __restrict__ tar,
             float* __restrict__ out)
{
    extern __shared__ char dsm[];
    __shared__ unsigned s_mm[4];

    const int tid  = threadIdx.x;
    const int bid  = blockIdx.x;
    const int lane = tid & 31;

    const unsigned raw = smem_u32(dsm);
    const unsigned s0  = (raw + 1023u) & ~1023u;
    char* sb = dsm + (s0 - raw);

    // ---- phase 0: zero out slice + all smem tiles/dummy ----
    for (int i = bid * TPB + tid; i < OUT_N; i += NBLK * TPB) out[i] = 0.0f;
    {
        uint4 z = {0, 0, 0, 0};
        uint4* zp = (uint4*)sb;
        for (int i = tid; i < SM_ZERO / 16; i += TPB) zp[i] = z;
    }
    if (tid < 4) s_mm[tid] = (tid & 1) ? 0u : 0xFFFFFFFFu;

    // ---- phase 1: global min/max over both full images ----
    unsigned rmn = 0xFFFFFFFFu, rmx = 0u, tmn = 0xFFFFFFFFu, tmx = 0u;
    {
        const float4* r4p = (const float4*)ref;
        const float4* t4p = (const float4*)tar;
        const int n4 = NBATCH * NPIX / 4;
        for (int i = bid * TPB + tid; i < n4; i += NBLK * TPB) {
            float4 a = r4p[i];
            unsigned e;
            e = fenc(a.x); rmn = min(rmn, e); rmx = max(rmx, e);
            e = fenc(a.y); rmn = min(rmn, e); rmx = max(rmx, e);
            e = fenc(a.z); rmn = min(rmn, e); rmx = max(rmx, e);
            e = fenc(a.w); rmn = min(rmn, e); rmx = max(rmx, e);
            float4 b = t4p[i];
            e = fenc(b.x); tmn = min(tmn, e); tmx = max(tmx, e);
            e = fenc(b.y); tmn = min(tmn, e); tmx = max(tmx, e);
            e = fenc(b.z); tmn = min(tmn, e); tmx = max(tmx, e);
            e = fenc(b.w); tmn = min(tmn, e); tmx = max(tmx, e);
        }
    }
    #pragma unroll
    for (int o = 16; o > 0; o >>= 1) {
        rmn = min(rmn, __shfl_xor_sync(0xFFFFFFFFu, rmn, o));
        rmx = max(rmx, __shfl_xor_sync(0xFFFFFFFFu, rmx, o));
        tmn = min(tmn, __shfl_xor_sync(0xFFFFFFFFu, tmn, o));
        tmx = max(tmx, __shfl_xor_sync(0xFFFFFFFFu, tmx, o));
    }
    __syncthreads();
    if (lane == 0) {
        atomicMin(&s_mm[0], rmn); atomicMax(&s_mm[1], rmx);
        atomicMin(&s_mm[2], tmn); atomicMax(&s_mm[3], tmx);
    }
    __threadfence();
    __syncthreads();

    // ---- grid sync (144 CTAs, 1/SM, co-resident) ----
    if (tid == 0) {
        volatile unsigned* sl = g_slot[bid];
        sl[0] = s_mm[0]; sl[1] = s_mm[1]; sl[2] = s_mm[2]; sl[3] = s_mm[3];
        __threadfence();
        unsigned prev = atomicAdd(&g_cnt, 1);
        unsigned target = prev - (prev % NBLK) + NBLK;
        while (*(volatile unsigned*)&g_cnt < target) { }
        __threadfence();
    }
    __syncthreads();
    if (tid < 4) s_mm[tid] = (tid & 1) ? 0u : 0xFFFFFFFFu;
    __syncthreads();
    if (tid < NBLK) {
        volatile unsigned* sl = g_slot[tid];
        unsigned a0 = sl[0], a1 = sl[1], a2 = sl[2], a3 = sl[3];
        atomicMin(&s_mm[0], a0); atomicMax(&s_mm[1], a1);
        atomicMin(&s_mm[2], a2); atomicMax(&s_mm[3], a3);
    }
    __syncthreads();

    const float rmin = fdec(s_mm[0]), rmax = fdec(s_mm[1]);
    const float tmin = fdec(s_mm[2]), tmax = fdec(s_mm[3]);
    const float rs = 64.0f / (rmax - rmin);
    const float ts = 64.0f / (tmax - tmin);

    // ---- phase 2: scatter taps -> smem tiles, mma.sync accumulate ----
    const int batch = bid / BPB, sub = bid % BPB;
    const int lo = sub * CHUNK;
    const int hi = (lo + CHUNK < NPIX) ? lo + CHUNK : NPIX;
    const float* rp = ref + (size_t)batch * NPIX;
    const float* tp = tar + (size_t)batch * NPIX;

    const int set  = tid >> 9;            // 0 / 1
    const int t512 = tid & 511;
    const int ws   = t512 >> 5;           // warp in set 0..15
    const int px   = t512 & 255;
    const int half = t512 >> 8;           // taps {0,1} or {2,3}

    const unsigned baseA = s0 + set * SET_BYTES;
    const unsigned baseB = baseA + T_SZ;
    const unsigned dummy = s0 + DUMMY_OFF + tid * 8;

    // mma warp geometry: 8 warps cover 64x64, each 16 rows x 32 cols
    const int wm = ws >> 1, wn = ws & 1;
    const unsigned aAbase = baseA + (unsigned)(wm * 16 + (lane & 15)) * APITCH
                                  + (unsigned)((lane >> 4) << 4);
    const unsigned aBbase = baseB
        + (unsigned)(wn * 32 + (lane & 7) + ((lane >> 4) << 3)) * APITCH
        + (unsigned)(((lane >> 3) & 1) << 4);

    float c[16];
    #pragma unroll
    for (int i = 0; i < 16; i++) c[i] = 0.0f;

    unsigned pa[4] = {dummy, dummy + 2, dummy + 4, dummy + 6};
    const int barid = set + 1;

    for (int t = set; t < NT; t += 2) {
        // zero previous taps (other threads may claim these cells next)
        sts16(pa[0], 0); sts16(pa[1], 0); sts16(pa[2], 0); sts16(pa[3], 0);
        barset(barid);

        // compute + scatter 2 ref taps + 2 tar taps for pixel px
        unsigned ad[4] = {dummy, dummy + 2, dummy + 4, dummy + 6};
        unsigned short vv[4] = {0, 0, 0, 0};
        const int g = lo + t * KT + px;
        if (g < hi) {
            float r = rp[g], tv = tp[g];
            float fr = (r - rmin) * rs;
            float ft = (tv - tmin) * ts;
            float fir = floorf(fr), fit = floorf(ft);
            float ur = fr - fir, ut = ft - fit;
            int br = (int)fir - 1, bt = (int)fit - 1;
            #pragma unroll
            for (int q = 0; q < 2; q++) {
                int tap = half * 2 + q;
                int mA = br + tap, mB = bt + tap;
                if ((unsigned)mA < (unsigned)NBINS) {
                    ad[q] = baseA + (unsigned)mA * APITCH + (unsigned)px * 2;
                    vv[q] = __bfloat16_as_ushort(__float2bfloat16_rn(bw(ur, tap)));
                }
                if ((unsigned)mB < (unsigned)NBINS) {
                    ad[2 + q] = baseB + (unsigned)mB * APITCH + (unsigned)px * 2;
                    vv[2 + q] = __bfloat16_as_ushort(__float2bfloat16_rn(bw(ut, tap)));
                }
            }
        }
        sts16(ad[0], vv[0]); sts16(ad[1], vv[1]);
        sts16(ad[2], vv[2]); sts16(ad[3], vv[3]);
        pa[0] = ad[0]; pa[1] = ad[1]; pa[2] = ad[2]; pa[3] = ad[3];
        barset(barid);

        // mma over K=256 (16 ksteps), warps 0..7 of the set
        if (ws < 8) {
            #pragma unroll
            for (int ks = 0; ks < 16; ks++) {
                unsigned a[4], b[8];
                ldsm4(a, aAbase + ks * 32);
                ldsm4(b, aBbase + ks * 32);
                ldsm4(b + 4, aBbase + 16 * APITCH + ks * 32);
                mma16816(c + 0,  a, b[0], b[1]);
                mma16816(c + 4,  a, b[2], b[3]);
                mma16816(c + 8,  a, b[4], b[5]);
                mma16816(c + 12, a, b[6], b[7]);
            }
        }
        barset(barid);
    }

    // ---- phase 3: flush register accumulators (scale 4096 = 1/EPS^2) ----
    if (ws < 8) {
        float* o = out + (size_t)batch * NBINS * NBINS;
        const int rbase = wm * 16 + (lane >> 2);
        const int cbase = wn * 32 + (lane & 3) * 2;
        #pragma unroll
        for (int j = 0; j < 4; j++) {
            int cc = cbase + j * 8;
            atomicAdd(&o[rbase * 64 + cc],           c[4 * j + 0] * 4096.0f);
            atomicAdd(&o[rbase * 64 + cc + 1],       c[4 * j + 1] * 4096.0f);
            atomicAdd(&o[(rbase + 8) * 64 + cc],     c[4 * j + 2] * 4096.0f);
            atomicAdd(&o[(rbase + 8) * 64 + cc + 1], c[4 * j + 3] * 4096.0f);
        }
    }
}

extern "C" void kernel_launch(void* const* d_in, const int* in_sizes, int n_in,
                              void* d_out, int out_size) {
    const float* img_ref = (const float*)d_in[0];
    const float* img_tar = (const float*)d_in[1];
    float* out = (float*)d_out;
    cudaFuncSetAttribute(k_fused, cudaFuncAttributeMaxDynamicSharedMemorySize, SMEM_BYTES);
    k_fused<<<NBLK, TPB, SMEM_BYTES>>>(img_ref, img_tar, out);
}

// round 15
// speedup vs baseline: 1.4937x; 1.4937x over previous
#include <cuda_runtime.h>
#include <cuda_bf16.h>

static constexpr int NPIX   = 256 * 256;
static constexpr int NBATCH = 16;
static constexpr int NBINS  = 64;
static constexpr int BPB    = 9;
static constexpr int NBLK   = BPB * NBATCH;   // 144 <= 148 SMs, 1 CTA/SM
static constexpr int TPB    = 1024;
static constexpr int OUT_N  = NBATCH * NBINS * NBINS;
static constexpr int CHUNK  = (NPIX + BPB - 1) / BPB;   // 7282 px per block

// --- MMA sub-path (warps 0..15) ---
static constexpr int KT     = 256;            // pixels per MMA tile
static constexpr int NT_M   = 13;             // tiles via MMA
static constexpr int MMA_PX = NT_M * KT;      // 3328 px (46%)
static constexpr int APITCH = 528;            // 512+16B pad, conflict-free ldmatrix
static constexpr int T_SZ   = 64 * APITCH;    // 33792 B per tile
static constexpr int TILES_B = 2 * T_SZ;      // A + B

// --- atomic sub-path (warps 16..31): shift-replicated packed histogram ---
static constexpr int ROWW = 17;
static constexpr int REPW = NBINS * ROWW;     // 1088 u64
static constexpr int HWORDS = 4 * REPW;       // 4352 u64 = 34816 B

static constexpr int HIST_OFF  = TILES_B;               // 67584 (1KB aligned)
static constexpr int DUMMY_OFF = HIST_OFF + HWORDS * 8; // 102400
static constexpr int SM_ZERO   = DUMMY_OFF + 512 * 8;   // 106496
static constexpr int SMEM_BYTES = SM_ZERO + 1024;

__device__ unsigned g_slot[NBLK][4];
__device__ unsigned g_cnt;

__device__ __forceinline__ unsigned fenc(float f) {
    unsigned b = __float_as_uint(f);
    return (b & 0x80000000u) ? ~b : (b | 0x80000000u);
}
__device__ __forceinline__ float fdec(unsigned e) {
    unsigned b = (e & 0x80000000u) ? (e & 0x7fffffffu) : ~e;
    return __uint_as_float(b);
}
__device__ __forceinline__ unsigned smem_u32(const void* p) {
    unsigned a;
    asm("{ .reg .u64 t; cvta.to.shared.u64 t, %1; cvt.u32.u64 %0, t; }"
        : "=r"(a) : "l"(p));
    return a;
}
__device__ __forceinline__ void sts16(unsigned a, unsigned short v) {
    asm volatile("st.shared.u16 [%0], %1;" :: "r"(a), "h"(v) : "memory");
}
__device__ __forceinline__ void bar_named(int id, int n) {
    asm volatile("bar.sync %0, %1;" :: "r"(id), "r"(n) : "memory");
}
__device__ __forceinline__ void ldsm4(unsigned* r, unsigned addr) {
    asm volatile("ldmatrix.sync.aligned.m8n8.x4.shared.b16 {%0,%1,%2,%3}, [%4];"
                 : "=r"(r[0]), "=r"(r[1]), "=r"(r[2]), "=r"(r[3]) : "r"(addr));
}
__device__ __forceinline__ void mma16816(float* c, const unsigned* a,
                                         unsigned b0, unsigned b1) {
    asm volatile(
        "mma.sync.aligned.m16n8k16.row.col.f32.bf16.bf16.f32 "
        "{%0,%1,%2,%3}, {%4,%5,%6,%7}, {%8,%9}, {%0,%1,%2,%3};"
        : "+f"(c[0]), "+f"(c[1]), "+f"(c[2]), "+f"(c[3])
        : "r"(a[0]), "r"(a[1]), "r"(a[2]), "r"(a[3]), "r"(b0), "r"(b1));
}

__device__ __forceinline__ float bw(float u, int tap) {
    float v = 1.0f - u;
    if (tap == 0) return v * v * v * (1.0f / 6.0f);
    if (tap == 1) return fmaf(-u * u, fmaf(-0.5f, u, 1.0f), 2.0f / 3.0f);
    if (tap == 2) return fmaf(-v * v, fmaf(-0.5f, v, 1.0f), 2.0f / 3.0f);
    return u * u * u * (1.0f / 6.0f);
}

// Atomic engine: one pixel -> 4 u64 atomics into shift-replicated hist.
__device__ __forceinline__ void accum(float r, float t,
                                      float rmin, float rs,
                                      float tmin, float ts,
                                      unsigned long long* __restrict__ sh)
{
    float fr = (r - rmin) * rs;
    float ft = (t - tmin) * ts;
    float fir = floorf(fr), fit = floorf(ft);
    float ur = fr - fir,   ut = ft - fit;
    int br = (int)fir - 1;
    int bt = (int)fit - 1;

    float vr = 1.0f - ur, vt = 1.0f - ut;
    float urr = ur * ur, vrr = vr * vr, utt = ut * ut, vtt = vt * vt;

    float wr[4];
    wr[0] = vrr * vr * (1.0f / 6.0f);
    wr[1] = fmaf(-urr, fmaf(-0.5f, ur, 1.0f), 2.0f / 3.0f);
    wr[2] = fmaf(-vrr, fmaf(-0.5f, vr, 1.0f), 2.0f / 3.0f);
    wr[3] = urr * ur * (1.0f / 6.0f);

    float wt0 = vtt * vt * (4096.0f / 6.0f);
    float wt1 = fmaf(-utt, fmaf(-0.5f, ut, 1.0f), 2.0f / 3.0f) * 4096.0f;
    float wt2 = fmaf(-vtt, fmaf(-0.5f, vt, 1.0f), 2.0f / 3.0f) * 4096.0f;
    float wt3 = utt * ut * (4096.0f / 6.0f);

    const float MAGIC = 12582912.0f;
    int rep  = (-bt) & 3;
    int word = (bt + rep) >> 2;
    unsigned long long* base = sh + rep * REPW + word;

    #pragma unroll
    for (int i = 0; i < 4; i++) {
        int bi = br + i;
        if ((unsigned)bi >= (unsigned)NBINS) continue;
        float w = wr[i];
        unsigned m0 = __float_as_uint(fmaf(w, wt0, MAGIC));
        unsigned m1 = __float_as_uint(fmaf(w, wt1, MAGIC));
        unsigned m2 = __float_as_uint(fmaf(w, wt2, MAGIC));
        unsigned m3 = __float_as_uint(fmaf(w, wt3, MAGIC));
        unsigned lo = __byte_perm(m0, m1, 0x5410);
        unsigned hi = __byte_perm(m2, m3, 0x5410);
        unsigned long long P = ((unsigned long long)hi << 32) | lo;
        atomicAdd(base + bi * ROWW, P);
    }
}

__global__ __launch_bounds__(TPB, 1)
void k_fused(const float* __restrict__ ref,
             const float* __restrict__ tar,
             float* __restrict__ out)
{
    extern __shared__ char dsm[];
    __shared__ unsigned s_mm[4];

    const int tid  = threadIdx.x;
    const int bid  = blockIdx.x;
    const int lane = tid & 31;

    const unsigned raw = smem_u32(dsm);
    const unsigned s0  = (raw + 1023u) & ~1023u;
    char* sb = dsm + (s0 - raw);

    // ---- phase 0: zero out slice + all smem ----
    for (int i = bid * TPB + tid; i < OUT_N; i += NBLK * TPB) out[i] = 0.0f;
    {
        uint4 z = {0, 0, 0, 0};
        uint4* zp = (uint4*)sb;
        for (int i = tid; i < SM_ZERO / 16; i += TPB) zp[i] = z;
    }
    if (tid < 4) s_mm[tid] = (tid & 1) ? 0u : 0xFFFFFFFFu;

    // ---- phase 1: global min/max ----
    unsigned rmn = 0xFFFFFFFFu, rmx = 0u, tmn = 0xFFFFFFFFu, tmx = 0u;
    {
        const float4* r4p = (const float4*)ref;
        const float4* t4p = (const float4*)tar;
        const int n4 = NBATCH * NPIX / 4;
        for (int i = bid * TPB + tid; i < n4; i += NBLK * TPB) {
            float4 a = r4p[i];
            unsigned e;
            e = fenc(a.x); rmn = min(rmn, e); rmx = max(rmx, e);
            e = fenc(a.y); rmn = min(rmn, e); rmx = max(rmx, e);
            e = fenc(a.z); rmn = min(rmn, e); rmx = max(rmx, e);
            e = fenc(a.w); rmn = min(rmn, e); rmx = max(rmx, e);
            float4 b = t4p[i];
            e = fenc(b.x); tmn = min(tmn, e); tmx = max(tmx, e);
            e = fenc(b.y); tmn = min(tmn, e); tmx = max(tmx, e);
            e = fenc(b.z); tmn = min(tmn, e); tmx = max(tmx, e);
            e = fenc(b.w); tmn = min(tmn, e); tmx = max(tmx, e);
        }
    }
    #pragma unroll
    for (int o = 16; o > 0; o >>= 1) {
        rmn = min(rmn, __shfl_xor_sync(0xFFFFFFFFu, rmn, o));
        rmx = max(rmx, __shfl_xor_sync(0xFFFFFFFFu, rmx, o));
        tmn = min(tmn, __shfl_xor_sync(0xFFFFFFFFu, tmn, o));
        tmx = max(tmx, __shfl_xor_sync(0xFFFFFFFFu, tmx, o));
    }
    __syncthreads();
    if (lane == 0) {
        atomicMin(&s_mm[0], rmn); atomicMax(&s_mm[1], rmx);
        atomicMin(&s_mm[2], tmn); atomicMax(&s_mm[3], tmx);
    }
    __threadfence();
    __syncthreads();

    // ---- grid sync (144 CTAs, 1/SM, co-resident) ----
    if (tid == 0) {
        volatile unsigned* sl = g_slot[bid];
        sl[0] = s_mm[0]; sl[1] = s_mm[1]; sl[2] = s_mm[2]; sl[3] = s_mm[3];
        __threadfence();
        unsigned prev = atomicAdd(&g_cnt, 1);
        unsigned target = prev - (prev % NBLK) + NBLK;
        while (*(volatile unsigned*)&g_cnt < target) { }
        __threadfence();
    }
    __syncthreads();
    if (tid < 4) s_mm[tid] = (tid & 1) ? 0u : 0xFFFFFFFFu;
    __syncthreads();
    if (tid < NBLK) {
        volatile unsigned* sl = g_slot[tid];
        unsigned a0 = sl[0], a1 = sl[1], a2 = sl[2], a3 = sl[3];
        atomicMin(&s_mm[0], a0); atomicMax(&s_mm[1], a1);
        atomicMin(&s_mm[2], a2); atomicMax(&s_mm[3], a3);
    }
    __syncthreads();

    const float rmin = fdec(s_mm[0]), rmax = fdec(s_mm[1]);
    const float tmin = fdec(s_mm[2]), tmax = fdec(s_mm[3]);
    const float rs = 64.0f / (rmax - rmin);
    const float ts = 64.0f / (tmax - tmin);

    const int batch = bid / BPB, sub = bid % BPB;
    const int lo = sub * CHUNK;
    const int hi = (lo + CHUNK < NPIX) ? lo + CHUNK : NPIX;
    const float* rp = ref + (size_t)batch * NPIX;
    const float* tp = tar + (size_t)batch * NPIX;
    float* o = out + (size_t)batch * NBINS * NBINS;

    if (tid < 512) {
        // ================= MMA group: first MMA_PX pixels ==================
        const int ws   = tid >> 5;         // 0..15
        const int px   = tid & 255;
        const int half = tid >> 8;         // taps {0,1} or {2,3}

        const unsigned baseA = s0;
        const unsigned baseB = s0 + T_SZ;
        const unsigned dummy = s0 + DUMMY_OFF + (unsigned)tid * 8;

        const int wm = ws >> 1, wn = ws & 1;
        const unsigned aAbase = baseA + (unsigned)(wm * 16 + (lane & 15)) * APITCH
                                      + (unsigned)((lane >> 4) << 4);
        const unsigned aBbase = baseB
            + (unsigned)(wn * 32 + (lane & 7) + ((lane >> 4) << 3)) * APITCH
            + (unsigned)(((lane >> 3) & 1) << 4);

        float c[16];
        #pragma unroll
        for (int i = 0; i < 16; i++) c[i] = 0.0f;

        unsigned pa[4] = {dummy, dummy + 2, dummy + 4, dummy + 6};

        for (int t = 0; t < NT_M; ++t) {
            sts16(pa[0], 0); sts16(pa[1], 0); sts16(pa[2], 0); sts16(pa[3], 0);
            bar_named(1, 512);

            unsigned ad[4] = {dummy, dummy + 2, dummy + 4, dummy + 6};
            unsigned short vv[4] = {0, 0, 0, 0};
            const int g = lo + t * KT + px;
            if (g < hi) {
                float r = rp[g], tv = tp[g];
                float fr = (r - rmin) * rs;
                float ft = (tv - tmin) * ts;
                float fir = floorf(fr), fit = floorf(ft);
                float ur = fr - fir, ut = ft - fit;
                int br = (int)fir - 1, bt = (int)fit - 1;
                #pragma unroll
                for (int q = 0; q < 2; q++) {
                    int tap = half * 2 + q;
                    int mA = br + tap, mB = bt + tap;
                    if ((unsigned)mA < (unsigned)NBINS) {
                        ad[q] = baseA + (unsigned)mA * APITCH + (unsigned)px * 2;
                        vv[q] = __bfloat16_as_ushort(__float2bfloat16_rn(bw(ur, tap)));
                    }
                    if ((unsigned)mB < (unsigned)NBINS) {
                        ad[2 + q] = baseB + (unsigned)mB * APITCH + (unsigned)px * 2;
                        vv[2 + q] = __bfloat16_as_ushort(__float2bfloat16_rn(bw(ut, tap)));
                    }
                }
            }
            sts16(ad[0], vv[0]); sts16(ad[1], vv[1]);
            sts16(ad[2], vv[2]); sts16(ad[3], vv[3]);
            pa[0] = ad[0]; pa[1] = ad[1]; pa[2] = ad[2]; pa[3] = ad[3];
            bar_named(1, 512);

            if (ws < 8) {
                #pragma unroll
                for (int ks = 0; ks < 16; ks++) {
                    unsigned a[4], b[8];
                    ldsm4(a, aAbase + ks * 32);
                    ldsm4(b, aBbase + ks * 32);
                    ldsm4(b + 4, aBbase + 16 * APITCH + ks * 32);
                    mma16816(c + 0,  a, b[0], b[1]);
                    mma16816(c + 4,  a, b[2], b[3]);
                    mma16816(c + 8,  a, b[4], b[5]);
                    mma16816(c + 12, a, b[6], b[7]);
                }
            }
            bar_named(1, 512);
        }

        // flush register accumulators (scale 4096 = 1/EPS^2)
        if (ws < 8) {
            const int rbase = wm * 16 + (lane >> 2);
            const int cbase = wn * 32 + (lane & 3) * 2;
            #pragma unroll
            for (int j = 0; j < 4; j++) {
                int cc = cbase + j * 8;
                atomicAdd(&o[rbase * 64 + cc],           c[4 * j + 0] * 4096.0f);
                atomicAdd(&o[rbase * 64 + cc + 1],       c[4 * j + 1] * 4096.0f);
                atomicAdd(&o[(rbase + 8) * 64 + cc],     c[4 * j + 2] * 4096.0f);
                atomicAdd(&o[(rbase + 8) * 64 + cc + 1], c[4 * j + 3] * 4096.0f);
            }
        }
    } else {
        // ================= Atomic group: remaining pixels ===================
        const int a_tid = tid - 512;       // 0..511
        unsigned long long* sh = (unsigned long long*)(sb + HIST_OFF);

        for (int g = lo + MMA_PX + a_tid; g < hi; g += 512)
            accum(rp[g], tp[g], rmin, rs, tmin, ts, sh);

        bar_named(2, 512);

        // combine 4 replicas, unpack (scale 4096 already applied), flush
        for (int c = a_tid; c < NBINS * NBINS; c += 512) {
            int row = c >> 6;
            int bt  = c & 63;
            unsigned acc = 0;
            #pragma unroll
            for (int r = 0; r < 4; r++) {
                int w = (bt + r) >> 2;
                int f = (bt + r) & 3;
                unsigned long long h = sh[r * REPW + row * ROWW + w];
                acc += (unsigned)(h >> (f * 16)) & 0xFFFFu;
            }
            atomicAdd(&o[c], (float)acc);
        }
    }
}

extern "C" void kernel_launch(void* const* d_in, const int* in_sizes, int n_in,
                              void* d_out, int out_size) {
    const float* img_ref = (const float*)d_in[0];
    const float* img_tar = (const float*)d_in[1];
    float* out = (float*)d_out;
    cudaFuncSetAttribute(k_fused, cudaFuncAttributeMaxDynamicSharedMemorySize, SMEM_BYTES);
    k_fused<<<NBLK, TPB, SMEM_BYTES>>>(img_ref, img_tar, out);
}

// round 16
// speedup vs baseline: 1.5772x; 1.0559x over previous
#include <cuda_runtime.h>

static constexpr int NPIX   = 256 * 256;
static constexpr int NBATCH = 16;
static constexpr int NBINS  = 64;
static constexpr int BPB    = 9;
static constexpr int NBLK   = BPB * NBATCH;   // 144 <= 148 SMs, 1 CTA/SM
static constexpr int TPB    = 1024;
static constexpr int OUT_N  = NBATCH * NBINS * NBINS;
static constexpr int CHUNK  = (NPIX + BPB - 1) / BPB;   // 7282 px per block
static constexpr int GPX    = CHUNK / 2;                // pixels via L2-REDG engine

// Shift-replicated packed histogram geometry (16-bit fields, scale 4096):
// replica r stores bin b at word (b+r)>>2, field (b+r)&3. 17 words per ref-row.
static constexpr int ROWW = 17;
static constexpr int REPW = NBINS * ROWW;     // 1088 u64 per replica
static constexpr int HWORDS = 4 * REPW;       // 4352 u64 = 34816 B

__device__ unsigned g_slot[NBLK][4];
__device__ unsigned g_cnt;
// Per-CTA global scratch histogram (L2-resident, ~5 MB total)
__device__ unsigned long long g_hist[NBLK][HWORDS];

__device__ __forceinline__ unsigned fenc(float f) {
    unsigned b = __float_as_uint(f);
    return (b & 0x80000000u) ? ~b : (b | 0x80000000u);
}
__device__ __forceinline__ float fdec(unsigned e) {
    unsigned b = (e & 0x80000000u) ? (e & 0x7fffffffu) : ~e;
    return __uint_as_float(b);
}
__device__ __forceinline__ void bar_named(int id, int n) {
    asm volatile("bar.sync %0, %1;" :: "r"(id), "r"(n) : "memory");
}

// One pixel: 4x4 B-spline outer product -> 4 packed u64 atomics (shift-replica).
// Works for both shared-memory (ATOMS) and global (RED.E) targets.
__device__ __forceinline__ void accum(float r, float t,
                                      float rmin, float rs,
                                      float tmin, float ts,
                                      unsigned long long* __restrict__ sh)
{
    float fr = (r - rmin) * rs;              // in [0, 64]
    float ft = (t - tmin) * ts;
    float fir = floorf(fr), fit = floorf(ft);
    float ur = fr - fir,   ut = ft - fit;
    int br = (int)fir - 1;                   // -1..63
    int bt = (int)fit - 1;                   // -1..63

    float vr = 1.0f - ur, vt = 1.0f - ut;
    float urr = ur * ur, vrr = vr * vr, utt = ut * ut, vtt = vt * vt;

    float wr[4];
    wr[0] = vrr * vr * (1.0f / 6.0f);
    wr[1] = fmaf(-urr, fmaf(-0.5f, ur, 1.0f), 2.0f / 3.0f);
    wr[2] = fmaf(-vrr, fmaf(-0.5f, vr, 1.0f), 2.0f / 3.0f);
    wr[3] = urr * ur * (1.0f / 6.0f);

    float wt0 = vtt * vt * (4096.0f / 6.0f);
    float wt1 = fmaf(-utt, fmaf(-0.5f, ut, 1.0f), 2.0f / 3.0f) * 4096.0f;
    float wt2 = fmaf(-vtt, fmaf(-0.5f, vt, 1.0f), 2.0f / 3.0f) * 4096.0f;
    float wt3 = utt * ut * (4096.0f / 6.0f);

    const float MAGIC = 12582912.0f;         // 1.5 * 2^23 round-to-nearest
    int rep  = (-bt) & 3;
    int word = (bt + rep) >> 2;              // 0..16
    unsigned long long* base = sh + rep * REPW + word;

    #pragma unroll
    for (int i = 0; i < 4; i++) {
        int bi = br + i;
        if ((unsigned)bi >= (unsigned)NBINS) continue;
        float w = wr[i];
        unsigned m0 = __float_as_uint(fmaf(w, wt0, MAGIC));
        unsigned m1 = __float_as_uint(fmaf(w, wt1, MAGIC));
        unsigned m2 = __float_as_uint(fmaf(w, wt2, MAGIC));
        unsigned m3 = __float_as_uint(fmaf(w, wt3, MAGIC));
        unsigned lo = __byte_perm(m0, m1, 0x5410);
        unsigned hi = __byte_perm(m2, m3, 0x5410);
        unsigned long long P = ((unsigned long long)hi << 32) | lo;
        atomicAdd(base + bi * ROWW, P);
    }
}

__global__ __launch_bounds__(TPB, 1)
void k_fused(const float* __restrict__ ref,
             const float* __restrict__ tar,
             float* __restrict__ out)
{
    __shared__ unsigned long long sh[HWORDS];   // 34 KB smem histogram
    __shared__ unsigned s_mm[4];
    const int tid  = threadIdx.x;
    const int bid  = blockIdx.x;
    const int lane = tid & 31;

    // ---- phase 0: zero out slice + smem hist + own gmem scratch ----
    for (int i = bid * TPB + tid; i < OUT_N; i += NBLK * TPB) out[i] = 0.0f;
    for (int i = tid; i < HWORDS; i += TPB) sh[i] = 0ull;
    {
        uint4 z = {0, 0, 0, 0};
        uint4* gz = (uint4*)g_hist[bid];
        for (int i = tid; i < HWORDS / 2; i += TPB) gz[i] = z;
    }
    if (tid < 4) s_mm[tid] = (tid & 1) ? 0u : 0xFFFFFFFFu;

    // ---- phase 1: global min/max over both full images ----
    unsigned rmn = 0xFFFFFFFFu, rmx = 0u, tmn = 0xFFFFFFFFu, tmx = 0u;
    {
        const float4* r4p = (const float4*)ref;
        const float4* t4p = (const float4*)tar;
        const int n4 = NBATCH * NPIX / 4;
        for (int i = bid * TPB + tid; i < n4; i += NBLK * TPB) {
            float4 a = r4p[i];
            unsigned e;
            e = fenc(a.x); rmn = min(rmn, e); rmx = max(rmx, e);
            e = fenc(a.y); rmn = min(rmn, e); rmx = max(rmx, e);
            e = fenc(a.z); rmn = min(rmn, e); rmx = max(rmx, e);
            e = fenc(a.w); rmn = min(rmn, e); rmx = max(rmx, e);
            float4 b = t4p[i];
            e = fenc(b.x); tmn = min(tmn, e); tmx = max(tmx, e);
            e = fenc(b.y); tmn = min(tmn, e); tmx = max(tmx, e);
            e = fenc(b.z); tmn = min(tmn, e); tmx = max(tmx, e);
            e = fenc(b.w); tmn = min(tmn, e); tmx = max(tmx, e);
        }
    }
    #pragma unroll
    for (int o = 16; o > 0; o >>= 1) {
        rmn = min(rmn, __shfl_xor_sync(0xFFFFFFFFu, rmn, o));
        rmx = max(rmx, __shfl_xor_sync(0xFFFFFFFFu, rmx, o));
        tmn = min(tmn, __shfl_xor_sync(0xFFFFFFFFu, tmn, o));
        tmx = max(tmx, __shfl_xor_sync(0xFFFFFFFFu, tmx, o));
    }
    __syncthreads();
    if (lane == 0) {
        atomicMin(&s_mm[0], rmn); atomicMax(&s_mm[1], rmx);
        atomicMin(&s_mm[2], tmn); atomicMax(&s_mm[3], tmx);
    }
    __threadfence();                       // out-zero + scratch-zero visible
    __syncthreads();

    // ---- grid sync (144 CTAs, 1/SM, co-resident) ----
    if (tid == 0) {
        volatile unsigned* sl = g_slot[bid];
        sl[0] = s_mm[0]; sl[1] = s_mm[1]; sl[2] = s_mm[2]; sl[3] = s_mm[3];
        __threadfence();
        unsigned prev = atomicAdd(&g_cnt, 1);
        unsigned target = prev - (prev % NBLK) + NBLK;
        while (*(volatile unsigned*)&g_cnt < target) { }
        __threadfence();
    }
    __syncthreads();
    if (tid < 4) s_mm[tid] = (tid & 1) ? 0u : 0xFFFFFFFFu;
    __syncthreads();
    if (tid < NBLK) {
        volatile unsigned* sl = g_slot[tid];
        unsigned a0 = sl[0], a1 = sl[1], a2 = sl[2], a3 = sl[3];
        atomicMin(&s_mm[0], a0); atomicMax(&s_mm[1], a1);
        atomicMin(&s_mm[2], a2); atomicMax(&s_mm[3], a3);
    }
    __syncthreads();

    const float rmin = fdec(s_mm[0]), rmax = fdec(s_mm[1]);
    const float tmin = fdec(s_mm[2]), tmax = fdec(s_mm[3]);
    const float rs = 64.0f / (rmax - rmin);
    const float ts = 64.0f / (tmax - tmin);

    const int batch = bid / BPB, sub = bid % BPB;
    const int lo = sub * CHUNK;
    const int hi = (lo + CHUNK < NPIX) ? lo + CHUNK : NPIX;
    const int mid = (lo + GPX < hi) ? lo + GPX : hi;
    const float* rp = ref + (size_t)batch * NPIX;
    const float* tp = tar + (size_t)batch * NPIX;
    float* o = out + (size_t)batch * NBINS * NBINS;

    if (tid < 512) {
        // ===== gmem engine (warps 0..15): RED.E.ADD.64 into own L2 scratch =====
        unsigned long long* gh = g_hist[bid];
        for (int g = lo + tid; g < mid; g += 512)
            accum(rp[g], tp[g], rmin, rs, tmin, ts, gh);

        __threadfence();                   // order REDs before read-back
        bar_named(1, 512);

        // read back own scratch (L2 hits), combine replicas, flush to out
        for (int c = tid; c < NBINS * NBINS; c += 512) {
            int row = c >> 6;
            int bt  = c & 63;
            unsigned acc = 0;
            #pragma unroll
            for (int r = 0; r < 4; r++) {
                int w = (bt + r) >> 2;
                int f = (bt + r) & 3;
                unsigned long long h = gh[r * REPW + row * ROWW + w];
                acc += (unsigned)(h >> (f * 16)) & 0xFFFFu;
            }
            if (acc) atomicAdd(&o[c], (float)acc);
        }
    } else {
        // ===== smem engine (warps 16..31): ATOMS into shared histogram =====
        const int a_tid = tid - 512;
        for (int g = mid + a_tid; g < hi; g += 512)
            accum(rp[g], tp[g], rmin, rs, tmin, ts, sh);

        bar_named(2, 512);

        for (int c = a_tid; c < NBINS * NBINS; c += 512) {
            int row = c >> 6;
            int bt  = c & 63;
            unsigned acc = 0;
            #pragma unroll
            for (int r = 0; r < 4; r++) {
                int w = (bt + r) >> 2;
                int f = (bt + r) & 3;
                unsigned long long h = sh[r * REPW + row * ROWW + w];
                acc += (unsigned)(h >> (f * 16)) & 0xFFFFu;
            }
            if (acc) atomicAdd(&o[c], (float)acc);
        }
    }
}

extern "C" void kernel_launch(void* const* d_in, const int* in_sizes, int n_in,
                              void* d_out, int out_size) {
    const float* img_ref = (const float*)d_in[0];
    const float* img_tar = (const float*)d_in[1];
    float* out = (float*)d_out;
    k_fused<<<NBLK, TPB>>>(img_ref, img_tar, out);
}

// round 17
// speedup vs baseline: 1.6888x; 1.0707x over previous
#include <cuda_runtime.h>

static constexpr int NPIX   = 256 * 256;
static constexpr int NBATCH = 16;
static constexpr int NBINS  = 64;
static constexpr int BPB    = 9;
static constexpr int NBLK   = BPB * NBATCH;   // 144 <= 148 SMs, 1 CTA/SM
static constexpr int TPB    = 1024;
static constexpr int OUT_N  = NBATCH * NBINS * NBINS;
static constexpr int CHUNK  = (NPIX + BPB - 1) / BPB;   // 7282 px per block

// Shift-replicated packed histogram (16-bit fields, scale 4096):
// replica r stores bin b at word (b+r)>>2, field (b+r)&3. 17 u64 per ref-row.
static constexpr int ROWW = 17;
static constexpr int REPW = NBINS * ROWW;     // 1088 u64 per replica
static constexpr int HWORDS = 4 * REPW;       // 4352 u64 = 34816 B

__device__ unsigned g_slot[NBLK][4];
__device__ unsigned g_cnt;
// Per-CTA L2 scratch histogram (~5 MB total, L2-resident)
__device__ unsigned long long g_hist[NBLK][HWORDS];

__device__ __forceinline__ unsigned fenc(float f) {
    unsigned b = __float_as_uint(f);
    return (b & 0x80000000u) ? ~b : (b | 0x80000000u);
}
__device__ __forceinline__ float fdec(unsigned e) {
    unsigned b = (e & 0x80000000u) ? (e & 0x7fffffffu) : ~e;
    return __uint_as_float(b);
}

// One pixel -> 4 packed u64 adds into either the smem or the L2 histogram.
// Weight math is identical; only the atomic target differs (gm flag).
__device__ __forceinline__ void accum(float r, float t,
                                      float rmin, float rs,
                                      float tmin, float ts,
                                      unsigned long long* __restrict__ sh,
                                      unsigned long long* __restrict__ gh,
                                      bool gm)
{
    float fr = (r - rmin) * rs;              // in [0, 64]
    float ft = (t - tmin) * ts;
    float fir = floorf(fr), fit = floorf(ft);
    float ur = fr - fir,   ut = ft - fit;
    int br = (int)fir - 1;                   // -1..63
    int bt = (int)fit - 1;                   // -1..63

    float vr = 1.0f - ur, vt = 1.0f - ut;
    float urr = ur * ur, vrr = vr * vr, utt = ut * ut, vtt = vt * vt;

    float wr[4];
    wr[0] = vrr * vr * (1.0f / 6.0f);
    wr[1] = fmaf(-urr, fmaf(-0.5f, ur, 1.0f), 2.0f / 3.0f);
    wr[2] = fmaf(-vrr, fmaf(-0.5f, vr, 1.0f), 2.0f / 3.0f);
    wr[3] = urr * ur * (1.0f / 6.0f);

    float wt0 = vtt * vt * (4096.0f / 6.0f);
    float wt1 = fmaf(-utt, fmaf(-0.5f, ut, 1.0f), 2.0f / 3.0f) * 4096.0f;
    float wt2 = fmaf(-vtt, fmaf(-0.5f, vt, 1.0f), 2.0f / 3.0f) * 4096.0f;
    float wt3 = utt * ut * (4096.0f / 6.0f);

    const float MAGIC = 12582912.0f;         // 1.5*2^23 round-to-nearest
    int rep  = (-bt) & 3;
    int word = (bt + rep) >> 2;              // 0..16
    const int base = rep * REPW + word;

    // payloads + offsets for the 4 ref taps (shared between targets)
    unsigned long long P[4];
    int off[4];
    bool ok[4];
    #pragma unroll
    for (int i = 0; i < 4; i++) {
        int bi = br + i;
        ok[i] = (unsigned)bi < (unsigned)NBINS;
        off[i] = base + bi * ROWW;
        float w = wr[i];
        unsigned m0 = __float_as_uint(fmaf(w, wt0, MAGIC));
        unsigned m1 = __float_as_uint(fmaf(w, wt1, MAGIC));
        unsigned m2 = __float_as_uint(fmaf(w, wt2, MAGIC));
        unsigned m3 = __float_as_uint(fmaf(w, wt3, MAGIC));
        unsigned lo = __byte_perm(m0, m1, 0x5410);
        unsigned hi = __byte_perm(m2, m3, 0x5410);
        P[i] = ((unsigned long long)hi << 32) | lo;
    }
    if (gm) {
        #pragma unroll
        for (int i = 0; i < 4; i++)
            if (ok[i]) atomicAdd(gh + off[i], P[i]);   // RED.E.ADD.64 (L2)
    } else {
        #pragma unroll
        for (int i = 0; i < 4; i++)
            if (ok[i]) atomicAdd(sh + off[i], P[i]);   // ATOMS.ADD.64 (smem)
    }
}

__global__ __launch_bounds__(TPB, 1)
void k_fused(const float4* __restrict__ ref,
             const float4* __restrict__ tar,
             float* __restrict__ out)
{
    __shared__ unsigned long long sh[HWORDS];   // 34 KB smem histogram
    __shared__ unsigned s_mm[4];
    const int tid  = threadIdx.x;
    const int bid  = blockIdx.x;
    const int lane = tid & 31;

    // ---- phase 0: zero out slice + smem hist + own L2 scratch ----
    for (int i = bid * TPB + tid; i < OUT_N; i += NBLK * TPB) out[i] = 0.0f;
    for (int i = tid; i < HWORDS; i += TPB) sh[i] = 0ull;
    {
        uint4 z = {0, 0, 0, 0};
        uint4* gz = (uint4*)g_hist[bid];
        for (int i = tid; i < HWORDS / 2; i += TPB) gz[i] = z;
    }
    if (tid < 4) s_mm[tid] = (tid & 1) ? 0u : 0xFFFFFFFFu;

    // ---- phase 1: global min/max over both full images ----
    unsigned rmn = 0xFFFFFFFFu, rmx = 0u, tmn = 0xFFFFFFFFu, tmx = 0u;
    const int n4 = NBATCH * NPIX / 4;
    for (int i = bid * TPB + tid; i < n4; i += NBLK * TPB) {
        float4 a = ref[i];
        unsigned e;
        e = fenc(a.x); rmn = min(rmn, e); rmx = max(rmx, e);
        e = fenc(a.y); rmn = min(rmn, e); rmx = max(rmx, e);
        e = fenc(a.z); rmn = min(rmn, e); rmx = max(rmx, e);
        e = fenc(a.w); rmn = min(rmn, e); rmx = max(rmx, e);
        float4 b = tar[i];
        e = fenc(b.x); tmn = min(tmn, e); tmx = max(tmx, e);
        e = fenc(b.y); tmn = min(tmn, e); tmx = max(tmx, e);
        e = fenc(b.z); tmn = min(tmn, e); tmx = max(tmx, e);
        e = fenc(b.w); tmn = min(tmn, e); tmx = max(tmx, e);
    }
    #pragma unroll
    for (int o = 16; o > 0; o >>= 1) {
        rmn = min(rmn, __shfl_xor_sync(0xFFFFFFFFu, rmn, o));
        rmx = max(rmx, __shfl_xor_sync(0xFFFFFFFFu, rmx, o));
        tmn = min(tmn, __shfl_xor_sync(0xFFFFFFFFu, tmn, o));
        tmx = max(tmx, __shfl_xor_sync(0xFFFFFFFFu, tmx, o));
    }
    __syncthreads();
    if (lane == 0) {
        atomicMin(&s_mm[0], rmn); atomicMax(&s_mm[1], rmx);
        atomicMin(&s_mm[2], tmn); atomicMax(&s_mm[3], tmx);
    }
    __threadfence();                       // out-zero + scratch-zero visible
    __syncthreads();

    // ---- grid sync (144 CTAs, 1/SM, co-resident) ----
    if (tid == 0) {
        volatile unsigned* sl = g_slot[bid];
        sl[0] = s_mm[0]; sl[1] = s_mm[1]; sl[2] = s_mm[2]; sl[3] = s_mm[3];
        __threadfence();
        unsigned prev = atomicAdd(&g_cnt, 1);
        unsigned target = prev - (prev % NBLK) + NBLK;
        while (*(volatile unsigned*)&g_cnt < target) { }
        __threadfence();
    }
    __syncthreads();
    if (tid < 4) s_mm[tid] = (tid & 1) ? 0u : 0xFFFFFFFFu;
    __syncthreads();
    if (tid < NBLK) {
        volatile unsigned* sl = g_slot[tid];
        unsigned a0 = sl[0], a1 = sl[1], a2 = sl[2], a3 = sl[3];
        atomicMin(&s_mm[0], a0); atomicMax(&s_mm[1], a1);
        atomicMin(&s_mm[2], a2); atomicMax(&s_mm[3], a3);
    }
    __syncthreads();

    const float rmin = fdec(s_mm[0]), rmax = fdec(s_mm[1]);
    const float tmin = fdec(s_mm[2]), tmax = fdec(s_mm[3]);
    const float rs = 64.0f / (rmax - rmin);
    const float ts = 64.0f / (tmax - tmin);

    // ---- phase 2: dual-sink histogram (lane-interleaved 37.5% -> L2) ----
    const int batch = bid / BPB, sub = bid % BPB;
    const float4* rp = ref + (size_t)batch * (NPIX / 4);
    const float4* tp = tar + (size_t)batch * (NPIX / 4);
    unsigned long long* gh = g_hist[bid];
    const bool gm = (lane & 7) < 3;        // 12/32 lanes offload to L2

    for (int i = sub * TPB + tid; i < NPIX / 4; i += BPB * TPB) {
        float4 r4 = rp[i];
        float4 t4 = tp[i];
        accum(r4.x, t4.x, rmin, rs, tmin, ts, sh, gh, gm);
        accum(r4.y, t4.y, rmin, rs, tmin, ts, sh, gh, gm);
        accum(r4.z, t4.z, rmin, rs, tmin, ts, sh, gh, gm);
        accum(r4.w, t4.w, rmin, rs, tmin, ts, sh, gh, gm);
    }
    __threadfence();                       // REDs visible before read-back
    __syncthreads();

    // ---- phase 3: combine replicas from BOTH sinks, flush to out ----
    float* o = out + (size_t)batch * NBINS * NBINS;
    for (int c = tid; c < NBINS * NBINS; c += TPB) {
        int row = c >> 6;
        int bt  = c & 63;
        unsigned acc = 0;
        #pragma unroll
        for (int r = 0; r < 4; r++) {
            int w = (bt + r) >> 2;
            int f = (bt + r) & 3;
            int idx = r * REPW + row * ROWW + w;
            acc += (unsigned)(sh[idx] >> (f * 16)) & 0xFFFFu;
            acc += (unsigned)(gh[idx] >> (f * 16)) & 0xFFFFu;
        }
        atomicAdd(&o[c], (float)acc);
    }
}

extern "C" void kernel_launch(void* const* d_in, const int* in_sizes, int n_in,
                              void* d_out, int out_size) {
    const float4* img_ref = (const float4*)d_in[0];
    const float4* img_tar = (const float4*)d_in[1];
    float* out = (float*)d_out;
    k_fused<<<NBLK, TPB>>>(img_ref, img_tar, out);
}